// round 12
// baseline (speedup 1.0000x reference)
#include <cuda_runtime.h>
#include <cuda_fp16.h>
#include <cstdint>

#define N_DRUG 25000
#define N_DIS  25000
#define NN     50000
#define NE     800000
#define D      128
#define DH     (D / 2)     // half2 per row

// Scratch: __device__ globals (no allocations allowed).
__device__ int            g_cnt[NN];                       // integer degrees
__device__ int            g_rowptr[NN + 1];                // CSR row pointers
__device__ int            g_wr[NN];                        // bucket write cursors
__device__ unsigned short g_ecol16[NE];                    // CSR cols (uint16)
__device__ __align__(16) __half2 g_h2[(size_t)NN * DH];    // src-norm-scaled fp16 features

static __device__ __forceinline__ int clamp_idx(int v) {
    return v < 0 ? 0 : (v >= NN ? NN - 1 : v);
}

// ---------------------------------------------------------------------------
// Zero the degree counters (output needs no init: gather writes every row).
// ---------------------------------------------------------------------------
__global__ void zero_kernel() {
    int i = blockIdx.x * blockDim.x + threadIdx.x;
    if (i < NN) g_cnt[i] = 0;
}

// ---------------------------------------------------------------------------
// Integer degree histogram: grid-stride, 4 edges per thread via int4.
// ---------------------------------------------------------------------------
__global__ void degree_kernel(const int4* __restrict__ rows4) {
    const int stride = gridDim.x * blockDim.x;
    for (int i = blockIdx.x * blockDim.x + threadIdx.x; i < NE / 4; i += stride) {
        int4 r = rows4[i];
        atomicAdd(&g_cnt[clamp_idx(r.x)], 1);
        atomicAdd(&g_cnt[clamp_idx(r.y)], 1);
        atomicAdd(&g_cnt[clamp_idx(r.z)], 1);
        atomicAdd(&g_cnt[clamp_idx(r.w)], 1);
    }
}

// ---------------------------------------------------------------------------
// Exclusive prefix scan of g_cnt -> g_rowptr, g_wr.  Single 1024-thread block.
// ---------------------------------------------------------------------------
#define SCAN_T 1024
#define CHUNK  ((NN + SCAN_T - 1) / SCAN_T)   // 49

__global__ __launch_bounds__(SCAN_T)
void scan_kernel() {
    __shared__ int wsum[32];
    const int t    = threadIdx.x;
    const int lane = t & 31;
    const int wid  = t >> 5;
    const int base = t * CHUNK;

    int s = 0;
    #pragma unroll
    for (int i = 0; i < CHUNK; ++i) {
        int idx = base + i;
        if (idx < NN) s += g_cnt[idx];
    }
    int v = s;
    #pragma unroll
    for (int o = 1; o < 32; o <<= 1) {
        int n = __shfl_up_sync(0xffffffffu, v, o);
        if (lane >= o) v += n;
    }
    if (lane == 31) wsum[wid] = v;
    __syncthreads();
    if (wid == 0) {
        int w = wsum[lane];
        #pragma unroll
        for (int o = 1; o < 32; o <<= 1) {
            int n = __shfl_up_sync(0xffffffffu, w, o);
            if (lane >= o) w += n;
        }
        wsum[lane] = w;
    }
    __syncthreads();

    int run = (v - s) + (wid > 0 ? wsum[wid - 1] : 0);   // exclusive prefix
    #pragma unroll
    for (int i = 0; i < CHUNK; ++i) {
        int idx = base + i;
        if (idx < NN) {
            g_rowptr[idx] = run;
            g_wr[idx]     = run;
            run += g_cnt[idx];
        }
    }
    if (t == 0) g_rowptr[NN] = NE;
}

// ---------------------------------------------------------------------------
// Bucket edges by destination row, storing uint16 column indices.
// ---------------------------------------------------------------------------
__global__ __launch_bounds__(256)
void bucket_kernel(const int4* __restrict__ rows4, const int4* __restrict__ cols4) {
    const int stride = gridDim.x * blockDim.x;
    for (int i = blockIdx.x * blockDim.x + threadIdx.x; i < NE / 4; i += stride) {
        int4 r = rows4[i];
        int4 c = cols4[i];
        int p;
        p = atomicAdd(&g_wr[clamp_idx(r.x)], 1); g_ecol16[p] = (unsigned short)clamp_idx(c.x);
        p = atomicAdd(&g_wr[clamp_idx(r.y)], 1); g_ecol16[p] = (unsigned short)clamp_idx(c.y);
        p = atomicAdd(&g_wr[clamp_idx(r.z)], 1); g_ecol16[p] = (unsigned short)clamp_idx(c.z);
        p = atomicAdd(&g_wr[clamp_idx(r.w)], 1); g_ecol16[p] = (unsigned short)clamp_idx(c.w);
    }
}

// ---------------------------------------------------------------------------
// Register-tiled projection (fp32 math, fp16 store with source-side norm):
//   g_h2[base+row][:] = half( (f[row] @ W) * norm[base+row] )
// ---------------------------------------------------------------------------
#define BM 64
#define TM 8
#define TN 4
#define PROJ_TB 256

extern __shared__ float s_proj[];

__global__ __launch_bounds__(PROJ_TB, 2)
void project_kernel(const float* __restrict__ drug_f, const float* __restrict__ dis_f,
                    const float* __restrict__ drug_w, const float* __restrict__ dis_w) {
    float* sW = s_proj;                 // [128][128]
    float* sF = s_proj + D * D;         // [BM][128]

    const int type = blockIdx.y;
    const float* __restrict__ f = type ? dis_f : drug_f;
    const float* __restrict__ W = type ? dis_w : drug_w;
    const int n_rows   = type ? N_DIS : N_DRUG;
    const int base     = type ? N_DRUG : 0;
    const int row_base = blockIdx.x * BM;

    const int tid = threadIdx.x;
    const int cg  = tid & 31;
    const int rg  = tid >> 5;

    {
        const float4* W4 = (const float4*)W;
        float4* sW4 = (float4*)sW;
        #pragma unroll
        for (int t = 0; t < (D * D / 4) / PROJ_TB; ++t)
            sW4[t * PROJ_TB + tid] = W4[t * PROJ_TB + tid];
    }
    {
        float4* sF4 = (float4*)sF;
        #pragma unroll
        for (int t = 0; t < (BM * D / 4) / PROJ_TB; ++t) {
            int idx = t * PROJ_TB + tid;
            int r   = idx >> 5;
            int k4  = idx & 31;
            int row = row_base + r;
            if (row >= n_rows) row = n_rows - 1;
            sF4[idx] = ((const float4*)f)[(size_t)row * 32 + k4];
        }
    }
    __syncthreads();

    float acc[TM][TN];
    #pragma unroll
    for (int i = 0; i < TM; ++i)
        #pragma unroll
        for (int j = 0; j < TN; ++j) acc[i][j] = 0.f;

    const int r0 = rg * TM;
    const int c0 = cg * TN;

    for (int k0 = 0; k0 < D; k0 += 4) {
        float4 a4[TM];
        #pragma unroll
        for (int i = 0; i < TM; ++i)
            a4[i] = *(const float4*)&sF[(r0 + i) * D + k0];
        float4 b4[4];
        #pragma unroll
        for (int kk = 0; kk < 4; ++kk)
            b4[kk] = *(const float4*)&sW[(k0 + kk) * D + c0];
        #pragma unroll
        for (int kk = 0; kk < 4; ++kk) {
            #pragma unroll
            for (int i = 0; i < TM; ++i) {
                float a = (kk == 0) ? a4[i].x : (kk == 1) ? a4[i].y
                        : (kk == 2) ? a4[i].z : a4[i].w;
                acc[i][0] += a * b4[kk].x;
                acc[i][1] += a * b4[kk].y;
                acc[i][2] += a * b4[kk].z;
                acc[i][3] += a * b4[kk].w;
            }
        }
    }

    #pragma unroll
    for (int i = 0; i < TM; ++i) {
        int row = row_base + r0 + i;
        if (row < n_rows) {
            int node = base + row;
            float nrm = rsqrtf(fmaxf((float)g_cnt[node], 1.0f));
            __half2 h0 = __floats2half2_rn(acc[i][0] * nrm, acc[i][1] * nrm);
            __half2 h1 = __floats2half2_rn(acc[i][2] * nrm, acc[i][3] * nrm);
            uint2 packed;
            packed.x = *(uint32_t*)&h0;
            packed.y = *(uint32_t*)&h1;
            *(uint2*)&g_h2[(size_t)node * DH + (c0 >> 1)] = packed;
        }
    }
}

// ---------------------------------------------------------------------------
// CSR gather: one warp per destination node.
//   - indices loaded COALESCED (one uint16 per lane covers 32 edges)
//   - index broadcast via shfl, 4 fp16 gathers (256B each) in flight
//   - dest norm fused; each output row written exactly ONCE (no atomics,
//     no output zeroing)
// ---------------------------------------------------------------------------
__global__ __launch_bounds__(256)
void gather_kernel(float* __restrict__ out) {
    const int node = blockIdx.x * 8 + (threadIdx.x >> 5);
    const int lane = threadIdx.x & 31;
    if (node >= NN) return;

    const int beg = g_rowptr[node];
    const int end = g_rowptr[node + 1];
    const int hoff = lane * 2;                 // half2 offset within a row

    float4 acc = make_float4(0.f, 0.f, 0.f, 0.f);

    for (int b = beg; b < end; b += 32) {
        const int nb = min(32, end - b);
        int myidx = (lane < nb) ? (int)g_ecol16[b + lane] : 0;   // coalesced

        int j = 0;
        for (; j + 4 <= nb; j += 4) {
            int c0 = __shfl_sync(0xffffffffu, myidx, j + 0);
            int c1 = __shfl_sync(0xffffffffu, myidx, j + 1);
            int c2 = __shfl_sync(0xffffffffu, myidx, j + 2);
            int c3 = __shfl_sync(0xffffffffu, myidx, j + 3);
            uint2 p0 = *(const uint2*)&g_h2[(size_t)c0 * DH + hoff];
            uint2 p1 = *(const uint2*)&g_h2[(size_t)c1 * DH + hoff];
            uint2 p2 = *(const uint2*)&g_h2[(size_t)c2 * DH + hoff];
            uint2 p3 = *(const uint2*)&g_h2[(size_t)c3 * DH + hoff];
            float2 a0 = __half22float2(*(__half2*)&p0.x), b0 = __half22float2(*(__half2*)&p0.y);
            float2 a1 = __half22float2(*(__half2*)&p1.x), b1 = __half22float2(*(__half2*)&p1.y);
            float2 a2 = __half22float2(*(__half2*)&p2.x), b2 = __half22float2(*(__half2*)&p2.y);
            float2 a3 = __half22float2(*(__half2*)&p3.x), b3 = __half22float2(*(__half2*)&p3.y);
            acc.x += (a0.x + a1.x) + (a2.x + a3.x);
            acc.y += (a0.y + a1.y) + (a2.y + a3.y);
            acc.z += (b0.x + b1.x) + (b2.x + b3.x);
            acc.w += (b0.y + b1.y) + (b2.y + b3.y);
        }
        for (; j < nb; ++j) {
            int c = __shfl_sync(0xffffffffu, myidx, j);
            uint2 p = *(const uint2*)&g_h2[(size_t)c * DH + hoff];
            float2 a = __half22float2(*(__half2*)&p.x), bb = __half22float2(*(__half2*)&p.y);
            acc.x += a.x; acc.y += a.y; acc.z += bb.x; acc.w += bb.y;
        }
    }

    const float nrm = rsqrtf(fmaxf((float)(end - beg), 1.0f));
    float4 r;
    r.x = acc.x * nrm; r.y = acc.y * nrm; r.z = acc.z * nrm; r.w = acc.w * nrm;
    *(float4*)&out[(size_t)node * D + lane * 4] = r;
}

// ---------------------------------------------------------------------------
// Launch sequence (stream 0, graph-capturable, allocation-free).
// Input order per metadata: drug_f, disease_f, drug_w, disease_w, rows, cols.
// ---------------------------------------------------------------------------
extern "C" void kernel_launch(void* const* d_in, const int* in_sizes, int n_in,
                              void* d_out, int out_size) {
    const float* drug_f = (const float*)d_in[0];
    const float* dis_f  = (const float*)d_in[1];
    const float* drug_w = (const float*)d_in[2];
    const float* dis_w  = (const float*)d_in[3];
    const int*   rows   = (const int*)d_in[4];
    const int*   cols   = (const int*)d_in[5];
    float* out = (float*)d_out;

    // 1) zero degree counters
    zero_kernel<<<(NN + 255) / 256, 256>>>();

    // 2) integer degree histogram
    degree_kernel<<<784, 256>>>((const int4*)rows);

    // 3) CSR row pointers (exclusive scan)
    scan_kernel<<<1, SCAN_T>>>();

    // 4) bucket edges (uint16 cols)
    bucket_kernel<<<784, 256>>>((const int4*)rows, (const int4*)cols);

    // 5) projection (+ source-side norm), fp16 store
    const int smem_bytes = (D * D + BM * D) * sizeof(float);   // 96 KB
    (void)cudaFuncSetAttribute(project_kernel,
                               cudaFuncAttributeMaxDynamicSharedMemorySize,
                               smem_bytes);
    dim3 pgrid((N_DRUG + BM - 1) / BM, 2);
    project_kernel<<<pgrid, PROJ_TB, smem_bytes>>>(drug_f, dis_f, drug_w, dis_w);

    // 6) CSR gather: coalesced uint16 indices, fp16 gathers, single store/row
    gather_kernel<<<(NN + 7) / 8, 256>>>(out);
}

// round 13
// speedup vs baseline: 1.6151x; 1.6151x over previous
#include <cuda_runtime.h>
#include <cuda_fp16.h>
#include <cstdint>

#define N_DRUG 25000
#define N_DIS  25000
#define NN     50000
#define NE     800000
#define D      128
#define DH     (D / 2)     // half2 per row

// Scratch: __device__ globals (no allocations allowed).
__device__ __align__(16) float   g_deg[NN];
__device__ __align__(16) __half2 g_h2[(size_t)NN * DH];  // src-norm-scaled fp16 features

static __device__ __forceinline__ int clamp_idx(int v) {
    return v < 0 ? 0 : (v >= NN ? NN - 1 : v);
}

// ---------------------------------------------------------------------------
// Zero output (poisoned 0xAA) + degree counters.
// ---------------------------------------------------------------------------
__global__ void zero_kernel(float4* __restrict__ out4) {
    const int stride = gridDim.x * blockDim.x;
    const int i0 = blockIdx.x * blockDim.x + threadIdx.x;
    const int total4 = NN * D / 4;
    const float4 z = make_float4(0.f, 0.f, 0.f, 0.f);
    for (int t = i0; t < total4; t += stride) out4[t] = z;
    for (int t = i0; t < NN; t += stride) g_deg[t] = 0.f;
}

// ---------------------------------------------------------------------------
// Degree histogram: grid-stride, 4 edges per thread via int4.
// ---------------------------------------------------------------------------
__global__ void degree_kernel(const int4* __restrict__ rows4) {
    const int stride = gridDim.x * blockDim.x;
    for (int i = blockIdx.x * blockDim.x + threadIdx.x; i < NE / 4; i += stride) {
        int4 r = rows4[i];
        atomicAdd(&g_deg[clamp_idx(r.x)], 1.0f);
        atomicAdd(&g_deg[clamp_idx(r.y)], 1.0f);
        atomicAdd(&g_deg[clamp_idx(r.z)], 1.0f);
        atomicAdd(&g_deg[clamp_idx(r.w)], 1.0f);
    }
}

// ---------------------------------------------------------------------------
// Tensor-core projection via mma.sync.m16n8k16 (fp16 in, fp32 accumulate):
//   g_h2[base+row][:] = half( (f[row] @ W) * norm[base+row] )
// Block: 128 rows x 128 cols, 8 warps (16-row strip per warp).
// Smem (fp16, stride 136 halves for conflict-free fragments):
//   sF [128][136], sWt[128][136] (W transposed: sWt[n][k] = W[k][n]).
// ---------------------------------------------------------------------------
#define PD 136                     // padded row stride in halves
#define PROJ_TB 256
#define PROJ_ROWS 128

__device__ __forceinline__ void mma16816(float c[4], const uint32_t a[4],
                                         uint32_t b0, uint32_t b1) {
    asm volatile(
        "mma.sync.aligned.m16n8k16.row.col.f32.f16.f16.f32 "
        "{%0,%1,%2,%3}, {%4,%5,%6,%7}, {%8,%9}, {%0,%1,%2,%3};\n"
        : "+f"(c[0]), "+f"(c[1]), "+f"(c[2]), "+f"(c[3])
        : "r"(a[0]), "r"(a[1]), "r"(a[2]), "r"(a[3]), "r"(b0), "r"(b1));
}

extern __shared__ __half s_h[];

__global__ __launch_bounds__(PROJ_TB, 2)
void project_mma_kernel(const float* __restrict__ drug_f, const float* __restrict__ dis_f,
                        const float* __restrict__ drug_w, const float* __restrict__ dis_w) {
    __half* sWt = s_h;                       // [128][PD]  sWt[n][k]
    __half* sF  = s_h + 128 * PD;            // [128][PD]  sF[r][k]

    const int type = blockIdx.y;
    const float* __restrict__ f = type ? dis_f : drug_f;
    const float* __restrict__ W = type ? dis_w : drug_w;
    const int n_rows   = type ? N_DIS : N_DRUG;
    const int base     = type ? N_DRUG : 0;
    const int row_base = blockIdx.x * PROJ_ROWS;

    const int tid  = threadIdx.x;
    const int wid  = tid >> 5;
    const int lane = tid & 31;
    const int gid  = lane >> 2;      // group id 0..7
    const int tg   = lane & 3;       // thread-in-group 0..3

    // Load W transposed into smem (coalesced global read).
    for (int idx = tid; idx < D * D; idx += PROJ_TB) {
        int k = idx >> 7, n = idx & 127;
        sWt[n * PD + k] = __float2half(W[idx]);
    }
    // Load the f tile (row-clamped for tail block).
    for (int idx = tid; idx < PROJ_ROWS * D; idx += PROJ_TB) {
        int r = idx >> 7, k = idx & 127;
        int row = row_base + r;
        if (row >= n_rows) row = n_rows - 1;
        sF[r * PD + k] = __float2half(f[(size_t)row * D + k]);
    }
    __syncthreads();

    const int rowA = wid * 16;       // warp's row strip within the block

    // Preload all A fragments: 8 k-tiles x 4 regs.
    uint32_t A[8][4];
    #pragma unroll
    for (int kt = 0; kt < 8; ++kt) {
        int bk = kt * 16 + tg * 2;
        A[kt][0] = *(const uint32_t*)&sF[(rowA + gid)     * PD + bk];
        A[kt][1] = *(const uint32_t*)&sF[(rowA + gid + 8) * PD + bk];
        A[kt][2] = *(const uint32_t*)&sF[(rowA + gid)     * PD + bk + 8];
        A[kt][3] = *(const uint32_t*)&sF[(rowA + gid + 8) * PD + bk + 8];
    }

    float acc[16][4];
    #pragma unroll
    for (int nt = 0; nt < 16; ++nt)
        #pragma unroll
        for (int j = 0; j < 4; ++j) acc[nt][j] = 0.f;

    #pragma unroll
    for (int nt = 0; nt < 16; ++nt) {
        const int n0 = nt * 8 + gid;
        #pragma unroll
        for (int kt = 0; kt < 8; ++kt) {
            uint32_t b0 = *(const uint32_t*)&sWt[n0 * PD + kt * 16 + tg * 2];
            uint32_t b1 = *(const uint32_t*)&sWt[n0 * PD + kt * 16 + tg * 2 + 8];
            mma16816(acc[nt], A[kt], b0, b1);
        }
    }

    // Store with fused source-side norm, fp16.
    const int r0 = row_base + rowA + gid;
    const int r1 = r0 + 8;
    if (r0 < n_rows) {
        int node = base + r0;
        float nrm = rsqrtf(fmaxf(g_deg[node], 1.0f));
        #pragma unroll
        for (int nt = 0; nt < 16; ++nt)
            g_h2[(size_t)node * DH + nt * 4 + tg] =
                __floats2half2_rn(acc[nt][0] * nrm, acc[nt][1] * nrm);
    }
    if (r1 < n_rows) {
        int node = base + r1;
        float nrm = rsqrtf(fmaxf(g_deg[node], 1.0f));
        #pragma unroll
        for (int nt = 0; nt < 16; ++nt)
            g_h2[(size_t)node * DH + nt * 4 + tg] =
                __floats2half2_rn(acc[nt][2] * nrm, acc[nt][3] * nrm);
    }
}

// ---------------------------------------------------------------------------
// Scatter: one warp per FOUR edges (unchanged from best-known R11 kernel).
//   - rows/cols fetched as one broadcast int4 each
//   - 4 independent fp16 gathers (uint2 = 4 halves per lane, 256B/edge)
//   - destination norm fused in
//   - accumulate fp32 via red.global.add.v4.f32
// ---------------------------------------------------------------------------
__global__ __launch_bounds__(256)
void edge_scatter_kernel(const int4* __restrict__ rows4,
                         const int4* __restrict__ cols4,
                         float* __restrict__ out) {
    const int w    = (blockIdx.x * blockDim.x + threadIdx.x) >> 5;  // warp = 4 edges
    const int lane = threadIdx.x & 31;
    if (w >= NE / 4) return;

    int4 rr = __ldg(&rows4[w]);   // lane-uniform -> broadcast
    int4 cc = __ldg(&cols4[w]);

    int r0 = clamp_idx(rr.x), r1 = clamp_idx(rr.y);
    int r2 = clamp_idx(rr.z), r3 = clamp_idx(rr.w);
    int c0 = clamp_idx(cc.x), c1 = clamp_idx(cc.y);
    int c2 = clamp_idx(cc.z), c3 = clamp_idx(cc.w);

    const int hoff = lane * 2;            // half2 index within row
    uint2 p0 = *(const uint2*)&g_h2[(size_t)c0 * DH + hoff];
    uint2 p1 = *(const uint2*)&g_h2[(size_t)c1 * DH + hoff];
    uint2 p2 = *(const uint2*)&g_h2[(size_t)c2 * DH + hoff];
    uint2 p3 = *(const uint2*)&g_h2[(size_t)c3 * DH + hoff];

    float n0 = rsqrtf(fmaxf(__ldg(&g_deg[r0]), 1.0f));
    float n1 = rsqrtf(fmaxf(__ldg(&g_deg[r1]), 1.0f));
    float n2 = rsqrtf(fmaxf(__ldg(&g_deg[r2]), 1.0f));
    float n3 = rsqrtf(fmaxf(__ldg(&g_deg[r3]), 1.0f));

    const size_t lo = (size_t)lane * 4;
    float* d0 = &out[(size_t)r0 * D + lo];
    float* d1 = &out[(size_t)r1 * D + lo];
    float* d2 = &out[(size_t)r2 * D + lo];
    float* d3 = &out[(size_t)r3 * D + lo];

    float2 a, b;
    a = __half22float2(*(__half2*)&p0.x); b = __half22float2(*(__half2*)&p0.y);
    asm volatile("red.global.add.v4.f32 [%0], {%1,%2,%3,%4};"
                 :: "l"(d0), "f"(a.x * n0), "f"(a.y * n0), "f"(b.x * n0), "f"(b.y * n0)
                 : "memory");
    a = __half22float2(*(__half2*)&p1.x); b = __half22float2(*(__half2*)&p1.y);
    asm volatile("red.global.add.v4.f32 [%0], {%1,%2,%3,%4};"
                 :: "l"(d1), "f"(a.x * n1), "f"(a.y * n1), "f"(b.x * n1), "f"(b.y * n1)
                 : "memory");
    a = __half22float2(*(__half2*)&p2.x); b = __half22float2(*(__half2*)&p2.y);
    asm volatile("red.global.add.v4.f32 [%0], {%1,%2,%3,%4};"
                 :: "l"(d2), "f"(a.x * n2), "f"(a.y * n2), "f"(b.x * n2), "f"(b.y * n2)
                 : "memory");
    a = __half22float2(*(__half2*)&p3.x); b = __half22float2(*(__half2*)&p3.y);
    asm volatile("red.global.add.v4.f32 [%0], {%1,%2,%3,%4};"
                 :: "l"(d3), "f"(a.x * n3), "f"(a.y * n3), "f"(b.x * n3), "f"(b.y * n3)
                 : "memory");
}

// ---------------------------------------------------------------------------
// Launch sequence (stream 0, graph-capturable, allocation-free).
// Input order per metadata: drug_f, disease_f, drug_w, disease_w, rows, cols.
// ---------------------------------------------------------------------------
extern "C" void kernel_launch(void* const* d_in, const int* in_sizes, int n_in,
                              void* d_out, int out_size) {
    const float* drug_f = (const float*)d_in[0];
    const float* dis_f  = (const float*)d_in[1];
    const float* drug_w = (const float*)d_in[2];
    const float* dis_w  = (const float*)d_in[3];
    const int*   rows   = (const int*)d_in[4];
    const int*   cols   = (const int*)d_in[5];
    float* out = (float*)d_out;

    // 1) zero output + degree counters
    zero_kernel<<<2048, 256>>>((float4*)out);

    // 2) degree histogram (4 edges/thread, grid-stride)
    degree_kernel<<<784, 256>>>((const int4*)rows);

    // 3) tensor-core projection (+ source-side norm), fp16 store
    const int smem_bytes = 2 * 128 * PD * sizeof(__half);   // 69632 B
    (void)cudaFuncSetAttribute(project_mma_kernel,
                               cudaFuncAttributeMaxDynamicSharedMemorySize,
                               smem_bytes);
    dim3 pgrid((N_DRUG + PROJ_ROWS - 1) / PROJ_ROWS, 2);
    project_mma_kernel<<<pgrid, PROJ_TB, smem_bytes>>>(drug_f, dis_f, drug_w, dis_w);

    // 4) edge scatter: 4 edges per warp, fp16 gather, fp32 vector reductions
    edge_scatter_kernel<<<NE / 4 / 8, 256>>>((const int4*)rows,
                                             (const int4*)cols, out);
}